// round 1
// baseline (speedup 1.0000x reference)
#include <cuda_runtime.h>
#include <cuda_bf16.h>

// Problem dims (fixed by reference setup_inputs)
#define BB 4
#define TE 512
#define TD 256
#define DM 256
#define TT 8   // t-rows per CTA in main kernel

// Scratch for projections (allocation-free: __device__ globals)
__device__ float g_Wenc[BB * TE * DM];   // [B,Te,D] = enc @ W_a
__device__ float g_Udec[BB * TD * DM];   // [B,Td,D] = dec @ U_a

__device__ __forceinline__ float fast_tanh(float x) {
    float y;
    asm("tanh.approx.f32 %0, %1;" : "=f"(y) : "f"(x));
    return y;
}

// ---------------------------------------------------------------------------
// Projection GEMM: Y[M,256] = X[M,256] @ W[256,256]
// BM=64, BN=64, BK=16, 256 threads, 4x4 per thread.
// dst==0 -> g_Wenc, dst==1 -> g_Udec. M implied by gridDim.x*64.
// ---------------------------------------------------------------------------
__global__ void __launch_bounds__(256)
proj_gemm(const float* __restrict__ X, const float* __restrict__ W, int dst) {
    float* __restrict__ Y = dst ? g_Udec : g_Wenc;

    __shared__ float sA[16][64];   // sA[k][m]
    __shared__ float sB[16][64];   // sB[k][n]

    const int tid = threadIdx.x;
    const int tx = tid & 15;          // n-sub
    const int ty = tid >> 4;          // m-sub
    const int m0 = blockIdx.x * 64;
    const int n0 = blockIdx.y * 64;

    float acc[4][4];
#pragma unroll
    for (int i = 0; i < 4; i++)
#pragma unroll
        for (int j = 0; j < 4; j++) acc[i][j] = 0.f;

    // load-index precompute
    const int lm  = tid >> 2;         // 0..63  (m row for A load)
    const int lkq = tid & 3;          // 0..3   (k quad for A load)
    const int lr  = tid >> 4;         // 0..15  (k row for B load)
    const int lc  = tid & 15;         // 0..15  (n quad for B load)

    for (int kt = 0; kt < 256; kt += 16) {
        // A tile: X[m0+lm][kt + 4*lkq .. +3] -> sA[k][m] (transposed)
        float4 av = *(const float4*)(X + (m0 + lm) * 256 + kt + 4 * lkq);
        sA[4 * lkq + 0][lm] = av.x;
        sA[4 * lkq + 1][lm] = av.y;
        sA[4 * lkq + 2][lm] = av.z;
        sA[4 * lkq + 3][lm] = av.w;
        // B tile: W[kt+lr][n0 + 4*lc .. +3] -> sB[k][n]
        float4 bv = *(const float4*)(W + (kt + lr) * 256 + n0 + 4 * lc);
        *(float4*)(&sB[lr][4 * lc]) = bv;
        __syncthreads();

#pragma unroll
        for (int kk = 0; kk < 16; kk++) {
            float4 a = *(const float4*)(&sA[kk][ty * 4]);
            float4 b = *(const float4*)(&sB[kk][tx * 4]);
            acc[0][0] += a.x * b.x; acc[0][1] += a.x * b.y; acc[0][2] += a.x * b.z; acc[0][3] += a.x * b.w;
            acc[1][0] += a.y * b.x; acc[1][1] += a.y * b.y; acc[1][2] += a.y * b.z; acc[1][3] += a.y * b.w;
            acc[2][0] += a.z * b.x; acc[2][1] += a.z * b.y; acc[2][2] += a.z * b.z; acc[2][3] += a.z * b.w;
            acc[3][0] += a.w * b.x; acc[3][1] += a.w * b.y; acc[3][2] += a.w * b.z; acc[3][3] += a.w * b.w;
        }
        __syncthreads();
    }

#pragma unroll
    for (int i = 0; i < 4; i++) {
        float4 o = make_float4(acc[i][0], acc[i][1], acc[i][2], acc[i][3]);
        *(float4*)(Y + (m0 + ty * 4 + i) * 256 + n0 + tx * 4) = o;
    }
}

// ---------------------------------------------------------------------------
// Main fused kernel: score (tanh) -> softmax -> context.
// Grid: B * (TD/TT) = 128 CTAs. 512 threads (16 warps).
// Warp w handles t = w&7, e parity = w>>3 (256 e's each).
// ---------------------------------------------------------------------------
__global__ void __launch_bounds__(512)
attn_main(const float* __restrict__ enc, const float* __restrict__ Va,
          float* __restrict__ out_ctx, float* __restrict__ out_attn) {
    __shared__ float s_udec[TT * DM];       // 8 KB
    __shared__ float s_v[DM];               // 1 KB
    __shared__ float s_score[TE][TT];       // 16 KB, e-major

    const int b  = blockIdx.x >> 5;
    const int t0 = (blockIdx.x & 31) * TT;
    const int tid = threadIdx.x;
    const int warp = tid >> 5;
    const int lane = tid & 31;

    // ---- Phase A: stage Udec rows + V into SMEM ----
    {
        const float4* src = (const float4*)(g_Udec + (b * TD + t0) * DM);
        ((float4*)s_udec)[tid] = src[tid];            // 512 * 16B = 8KB
        if (tid < 64) ((float4*)s_v)[tid] = ((const float4*)Va)[tid];
    }
    __syncthreads();

    // ---- Phase B: scores ----
    {
        const int t  = warp & 7;
        const int e0 = warp >> 3;                     // 0 or 1
        const float4* ud = (const float4*)(s_udec + t * DM);
        const float4 u0 = ud[lane];
        const float4 u1 = ud[lane + 32];
        const float4 v0 = ((const float4*)s_v)[lane];
        const float4 v1 = ((const float4*)s_v)[lane + 32];
        const float4* wenc = (const float4*)(g_Wenc + (size_t)b * TE * DM);

        for (int ei = 0; ei < TE / 2; ei++) {
            const int e = e0 + 2 * ei;
            float4 w0 = wenc[e * 64 + lane];
            float4 w1 = wenc[e * 64 + 32 + lane];
            float acc;
            acc  = v0.x * fast_tanh(w0.x + u0.x);
            acc += v0.y * fast_tanh(w0.y + u0.y);
            acc += v0.z * fast_tanh(w0.z + u0.z);
            acc += v0.w * fast_tanh(w0.w + u0.w);
            acc += v1.x * fast_tanh(w1.x + u1.x);
            acc += v1.y * fast_tanh(w1.y + u1.y);
            acc += v1.z * fast_tanh(w1.z + u1.z);
            acc += v1.w * fast_tanh(w1.w + u1.w);
#pragma unroll
            for (int off = 16; off > 0; off >>= 1)
                acc += __shfl_xor_sync(0xffffffffu, acc, off);
            if (lane == 0) s_score[e][t] = acc;
        }
    }
    __syncthreads();

    // ---- Phase C: softmax over e (warps 0..7, one t each) ----
    if (warp < 8) {
        const int t = warp;
        float vals[16];
        float mx = -1e30f;
#pragma unroll
        for (int k = 0; k < 16; k++) {
            vals[k] = s_score[lane + 32 * k][t];
            mx = fmaxf(mx, vals[k]);
        }
#pragma unroll
        for (int off = 16; off > 0; off >>= 1)
            mx = fmaxf(mx, __shfl_xor_sync(0xffffffffu, mx, off));
        float sum = 0.f;
#pragma unroll
        for (int k = 0; k < 16; k++) {
            vals[k] = exp2f((vals[k] - mx) * 1.4426950408889634f);
            sum += vals[k];
        }
#pragma unroll
        for (int off = 16; off > 0; off >>= 1)
            sum += __shfl_xor_sync(0xffffffffu, sum, off);
        const float inv = 1.0f / sum;
        float* arow = out_attn + ((size_t)(b * TD + t0 + t)) * TE;
#pragma unroll
        for (int k = 0; k < 16; k++) {
            const float w = vals[k] * inv;
            s_score[lane + 32 * k][t] = w;
            arow[lane + 32 * k] = w;
        }
    }
    __syncthreads();

    // ---- Phase D: context = attn @ enc ----
    {
        const int d = tid & 255;
        const int g = tid >> 8;                        // 0 or 1: t-group of 4
        const float* encb = enc + (size_t)b * TE * DM;
        float a0 = 0.f, a1 = 0.f, a2 = 0.f, a3 = 0.f;
#pragma unroll 4
        for (int e = 0; e < TE; e++) {
            const float ev = __ldg(encb + (size_t)e * DM + d);
            float4 aw = *(const float4*)(&s_score[e][g * 4]);
            a0 = fmaf(aw.x, ev, a0);
            a1 = fmaf(aw.y, ev, a1);
            a2 = fmaf(aw.z, ev, a2);
            a3 = fmaf(aw.w, ev, a3);
        }
        const int tr = t0 + g * 4;
        out_ctx[((size_t)(b * TD + tr + 0)) * DM + d] = a0;
        out_ctx[((size_t)(b * TD + tr + 1)) * DM + d] = a1;
        out_ctx[((size_t)(b * TD + tr + 2)) * DM + d] = a2;
        out_ctx[((size_t)(b * TD + tr + 3)) * DM + d] = a3;
    }
}

extern "C" void kernel_launch(void* const* d_in, const int* in_sizes, int n_in,
                              void* d_out, int out_size) {
    const float* enc = (const float*)d_in[0];   // [4,512,256]
    const float* dec = (const float*)d_in[1];   // [4,256,256]
    const float* Wa  = (const float*)d_in[2];   // [256,256]
    const float* Ua  = (const float*)d_in[3];   // [256,256]
    const float* Va  = (const float*)d_in[4];   // [256,1]

    float* out      = (float*)d_out;
    float* out_ctx  = out;                          // [4,256,256]
    float* out_attn = out + (size_t)BB * TD * DM;   // [4,256,512]

    // Projections (flattened over batch: weights shared)
    proj_gemm<<<dim3((BB * TE) / 64, DM / 64), 256>>>(enc, Wa, 0);
    proj_gemm<<<dim3((BB * TD) / 64, DM / 64), 256>>>(dec, Ua, 1);

    // Fused score/softmax/context
    attn_main<<<BB * (TD / TT), 512>>>(enc, Va, out_ctx, out_attn);
}

// round 2
// speedup vs baseline: 1.9189x; 1.9189x over previous
#include <cuda_runtime.h>
#include <cuda_bf16.h>
#include <cuda_fp16.h>

// Problem dims (fixed by reference setup_inputs)
#define BB 4
#define TE 512
#define TD 256
#define DM 256
#define TT 4   // t-rows per CTA in main kernel

// Scratch for projections (allocation-free: __device__ globals).
// +DM padding: attn_main prefetches one row past the end (values unused).
__device__ float g_Wenc[BB * TE * DM + DM];   // [B,Te,D] = enc @ W_a
__device__ float g_Udec[BB * TD * DM];        // [B,Td,D] = dec @ U_a

__device__ __forceinline__ __half2 htanh2(__half2 x) {
    unsigned xu = *reinterpret_cast<unsigned*>(&x);
    unsigned yu;
    asm("tanh.approx.f16x2 %0, %1;" : "=r"(yu) : "r"(xu));
    return *reinterpret_cast<__half2*>(&yu);
}

// ---------------------------------------------------------------------------
// Combined projection GEMM (both enc@W_a and dec@U_a in one launch).
// Rows 0..2047 -> g_Wenc, rows 2048..3071 -> g_Udec.
// BM=64, BN=64, BK=16, 256 threads, 4x4 per thread, double-buffered SMEM.
// grid = (3072/64, 256/64) = (48, 4) = 192 CTAs.
// ---------------------------------------------------------------------------
__global__ void __launch_bounds__(256)
proj_gemm2(const float* __restrict__ enc, const float* __restrict__ dec,
           const float* __restrict__ Wa,  const float* __restrict__ Ua) {
    __shared__ float sA[2][16][64];   // sA[p][k][m]
    __shared__ float sB[2][16][64];   // sB[p][k][n]

    const int tid = threadIdx.x;
    const int tx = tid & 15;          // n-sub
    const int ty = tid >> 4;          // m-sub
    const int row0 = blockIdx.x * 64;
    const int n0   = blockIdx.y * 64;

    const float* X;
    const float* W;
    float* Y;
    if (row0 < BB * TE) {
        X = enc + (size_t)row0 * DM;  W = Wa;  Y = g_Wenc + (size_t)row0 * DM;
    } else {
        const int r = row0 - BB * TE;
        X = dec + (size_t)r * DM;     W = Ua;  Y = g_Udec + (size_t)r * DM;
    }

    float acc[4][4];
#pragma unroll
    for (int i = 0; i < 4; i++)
#pragma unroll
        for (int j = 0; j < 4; j++) acc[i][j] = 0.f;

    // load-index precompute
    const int lm  = tid >> 2;         // 0..63  (m row for A load)
    const int lkq = tid & 3;          // 0..3   (k quad for A load)
    const int lr  = tid >> 4;         // 0..15  (k row for B load)
    const int lc  = tid & 15;         // 0..15  (n quad for B load)

    // prologue: tile 0
    float4 av = *(const float4*)(X + lm * DM + 4 * lkq);
    float4 bv = *(const float4*)(W + lr * DM + n0 + 4 * lc);
    sA[0][4 * lkq + 0][lm] = av.x;
    sA[0][4 * lkq + 1][lm] = av.y;
    sA[0][4 * lkq + 2][lm] = av.z;
    sA[0][4 * lkq + 3][lm] = av.w;
    *(float4*)(&sB[0][lr][4 * lc]) = bv;
    __syncthreads();

    int p = 0;
#pragma unroll 1
    for (int kt = 0; kt < 16; kt++) {
        float4 av2, bv2;
        if (kt < 15) {
            av2 = *(const float4*)(X + lm * DM + (kt + 1) * 16 + 4 * lkq);
            bv2 = *(const float4*)(W + ((kt + 1) * 16 + lr) * DM + n0 + 4 * lc);
        }
#pragma unroll
        for (int kk = 0; kk < 16; kk++) {
            float4 a = *(const float4*)(&sA[p][kk][ty * 4]);
            float4 b = *(const float4*)(&sB[p][kk][tx * 4]);
            acc[0][0] += a.x * b.x; acc[0][1] += a.x * b.y; acc[0][2] += a.x * b.z; acc[0][3] += a.x * b.w;
            acc[1][0] += a.y * b.x; acc[1][1] += a.y * b.y; acc[1][2] += a.y * b.z; acc[1][3] += a.y * b.w;
            acc[2][0] += a.z * b.x; acc[2][1] += a.z * b.y; acc[2][2] += a.z * b.z; acc[2][3] += a.z * b.w;
            acc[3][0] += a.w * b.x; acc[3][1] += a.w * b.y; acc[3][2] += a.w * b.z; acc[3][3] += a.w * b.w;
        }
        if (kt < 15) {
            sA[p ^ 1][4 * lkq + 0][lm] = av2.x;
            sA[p ^ 1][4 * lkq + 1][lm] = av2.y;
            sA[p ^ 1][4 * lkq + 2][lm] = av2.z;
            sA[p ^ 1][4 * lkq + 3][lm] = av2.w;
            *(float4*)(&sB[p ^ 1][lr][4 * lc]) = bv2;
        }
        __syncthreads();
        p ^= 1;
    }

#pragma unroll
    for (int i = 0; i < 4; i++) {
        float4 o = make_float4(acc[i][0], acc[i][1], acc[i][2], acc[i][3]);
        *(float4*)(Y + (ty * 4 + i) * DM + n0 + tx * 4) = o;
    }
}

// ---------------------------------------------------------------------------
// Main fused kernel: score (tanh.f16x2) -> softmax -> context.
// Grid: B * (TD/TT) = 256 CTAs. 512 threads (16 warps), 2 CTAs/SM.
// Phase B: warp w -> t = w&3, e-block (w>>2) of 128 e's.
// ---------------------------------------------------------------------------
__global__ void __launch_bounds__(512, 2)
attn_main(const float* __restrict__ enc, const float* __restrict__ Va,
          float* __restrict__ out_ctx, float* __restrict__ out_attn) {
    __shared__ float s_udec[TT * DM];       // 4 KB (reused as reduce buf in D)
    __shared__ float s_v[DM];               // 1 KB
    __shared__ float s_score[TE][TT];       // 8 KB, e-major

    const int b   = blockIdx.x >> 6;
    const int t0  = (blockIdx.x & 63) * TT;
    const int tid = threadIdx.x;
    const int warp = tid >> 5;
    const int lane = tid & 31;

    // ---- Phase A: stage Udec rows + V into SMEM ----
    if (tid < 256) {
        ((float4*)s_udec)[tid] = ((const float4*)(g_Udec + (b * TD + t0) * DM))[tid];
        if (tid < 64) ((float4*)s_v)[tid] = ((const float4*)Va)[tid];
    }
    __syncthreads();

    // ---- Phase B: scores with f16x2 tanh ----
    {
        const int t  = warp & 3;
        const int eg = warp >> 2;                     // 0..3, 128 e's each
        const float4* ud = (const float4*)(s_udec + t * DM);
        const float4 u0 = ud[lane];
        const float4 u1 = ud[lane + 32];
        const float4 v0 = ((const float4*)s_v)[lane];
        const float4 v1 = ((const float4*)s_v)[lane + 32];
        const __half2 vh0 = __floats2half2_rn(v0.x, v0.y);
        const __half2 vh1 = __floats2half2_rn(v0.z, v0.w);
        const __half2 vh2 = __floats2half2_rn(v1.x, v1.y);
        const __half2 vh3 = __floats2half2_rn(v1.z, v1.w);

        const float4* wp = (const float4*)(g_Wenc + (size_t)b * TE * DM)
                           + (size_t)(eg * 128) * 64;
        float4 w0 = wp[lane];
        float4 w1 = wp[lane + 32];

#pragma unroll 1
        for (int ei = 0; ei < 128; ei++) {
            const float4 c0 = w0, c1 = w1;
            // prefetch next row (padded overread on last iter; values unused)
            w0 = wp[(ei + 1) * 64 + lane];
            w1 = wp[(ei + 1) * 64 + 32 + lane];

            __half2 h0 = __floats2half2_rn(c0.x + u0.x, c0.y + u0.y);
            __half2 h1 = __floats2half2_rn(c0.z + u0.z, c0.w + u0.w);
            __half2 h2 = __floats2half2_rn(c1.x + u1.x, c1.y + u1.y);
            __half2 h3 = __floats2half2_rn(c1.z + u1.z, c1.w + u1.w);
            h0 = htanh2(h0);
            h1 = htanh2(h1);
            h2 = htanh2(h2);
            h3 = htanh2(h3);
            __half2 r = __hmul2(h0, vh0);
            r = __hfma2(h1, vh1, r);
            r = __hfma2(h2, vh2, r);
            r = __hfma2(h3, vh3, r);
            float2 rf = __half22float2(r);
            float acc = rf.x + rf.y;
#pragma unroll
            for (int off = 16; off > 0; off >>= 1)
                acc += __shfl_xor_sync(0xffffffffu, acc, off);
            if (lane == 0) s_score[eg * 128 + ei][t] = acc;
        }
    }
    __syncthreads();

    // ---- Phase C: softmax over e (warps 0..3, one t each) ----
    if (warp < TT) {
        const int t = warp;
        float vals[16];
        float mx = -1e30f;
#pragma unroll
        for (int k = 0; k < 16; k++) {
            vals[k] = s_score[lane + 32 * k][t];
            mx = fmaxf(mx, vals[k]);
        }
#pragma unroll
        for (int off = 16; off > 0; off >>= 1)
            mx = fmaxf(mx, __shfl_xor_sync(0xffffffffu, mx, off));
        float sum = 0.f;
#pragma unroll
        for (int k = 0; k < 16; k++) {
            vals[k] = exp2f((vals[k] - mx) * 1.4426950408889634f);
            sum += vals[k];
        }
#pragma unroll
        for (int off = 16; off > 0; off >>= 1)
            sum += __shfl_xor_sync(0xffffffffu, sum, off);
        const float inv = 1.0f / sum;
        float* arow = out_attn + ((size_t)(b * TD + t0 + t)) * TE;
#pragma unroll
        for (int k = 0; k < 16; k++) {
            const float w = vals[k] * inv;
            s_score[lane + 32 * k][t] = w;
            arow[lane + 32 * k] = w;
        }
    }
    __syncthreads();

    // ---- Phase D: context = attn @ enc (e-range split across thread halves) ----
    {
        const int d = tid & 255;
        const int h = tid >> 8;                        // 0 or 1: e-half
        const float* encb = enc + (size_t)b * TE * DM + (size_t)h * 256 * DM;
        float a0 = 0.f, a1 = 0.f, a2 = 0.f, a3 = 0.f;
#pragma unroll 4
        for (int e = 0; e < 256; e++) {
            const float ev = __ldg(encb + (size_t)e * DM + d);
            float4 aw = *(const float4*)(&s_score[h * 256 + e][0]);
            a0 = fmaf(aw.x, ev, a0);
            a1 = fmaf(aw.y, ev, a1);
            a2 = fmaf(aw.z, ev, a2);
            a3 = fmaf(aw.w, ev, a3);
        }
        // combine halves via SMEM (reuse s_udec: done with it after Phase B)
        float* red = s_udec;                           // [4][256]
        if (h == 1) {
            red[0 * 256 + d] = a0;
            red[1 * 256 + d] = a1;
            red[2 * 256 + d] = a2;
            red[3 * 256 + d] = a3;
        }
        __syncthreads();
        if (h == 0) {
            a0 += red[0 * 256 + d];
            a1 += red[1 * 256 + d];
            a2 += red[2 * 256 + d];
            a3 += red[3 * 256 + d];
            out_ctx[((size_t)(b * TD + t0 + 0)) * DM + d] = a0;
            out_ctx[((size_t)(b * TD + t0 + 1)) * DM + d] = a1;
            out_ctx[((size_t)(b * TD + t0 + 2)) * DM + d] = a2;
            out_ctx[((size_t)(b * TD + t0 + 3)) * DM + d] = a3;
        }
    }
}

extern "C" void kernel_launch(void* const* d_in, const int* in_sizes, int n_in,
                              void* d_out, int out_size) {
    const float* enc = (const float*)d_in[0];   // [4,512,256]
    const float* dec = (const float*)d_in[1];   // [4,256,256]
    const float* Wa  = (const float*)d_in[2];   // [256,256]
    const float* Ua  = (const float*)d_in[3];   // [256,256]
    const float* Va  = (const float*)d_in[4];   // [256,1]

    float* out      = (float*)d_out;
    float* out_ctx  = out;                          // [4,256,256]
    float* out_attn = out + (size_t)BB * TD * DM;   // [4,256,512]

    // Combined projections: 192 CTAs
    proj_gemm2<<<dim3((BB * TE + BB * TD) / 64, DM / 64), 256>>>(enc, dec, Wa, Ua);

    // Fused score/softmax/context: 256 CTAs
    attn_main<<<BB * (TD / TT), 512>>>(enc, Va, out_ctx, out_attn);
}

// round 3
// speedup vs baseline: 2.0743x; 1.0810x over previous
#include <cuda_runtime.h>
#include <cuda_bf16.h>
#include <cuda_fp16.h>

// Problem dims (fixed by reference setup_inputs)
#define BB 4
#define TE 512
#define TD 256
#define DM 256
#define TT 4   // t-rows per CTA in main kernel

// Scratch for projections in HALF (allocation-free: __device__ globals).
// +2*DM pad: attn_main prefetches 2 rows past the end (values unused).
__device__ __align__(16) __half g_WencH[BB * TE * DM + 2 * DM];
__device__ __align__(16) __half g_UdecH[BB * TD * DM];

__device__ __forceinline__ __half2 htanh2(__half2 x) {
    unsigned xu = *reinterpret_cast<unsigned*>(&x);
    unsigned yu;
    asm("tanh.approx.f16x2 %0, %1;" : "=r"(yu) : "r"(xu));
    return *reinterpret_cast<__half2*>(&yu);
}

// ---------------------------------------------------------------------------
// Combined projection GEMM (enc@W_a and dec@U_a in one launch), HALF output.
// Rows 0..2047 -> g_WencH, rows 2048..3071 -> g_UdecH.
// BM=64, BN=64, BK=16, 256 threads, 4x4/thread, double-buffered SMEM.
// ---------------------------------------------------------------------------
__global__ void __launch_bounds__(256)
proj_gemm2(const float* __restrict__ enc, const float* __restrict__ dec,
           const float* __restrict__ Wa,  const float* __restrict__ Ua) {
    __shared__ float sA[2][16][64];   // sA[p][k][m]
    __shared__ float sB[2][16][64];   // sB[p][k][n]

    const int tid = threadIdx.x;
    const int tx = tid & 15;          // n-sub
    const int ty = tid >> 4;          // m-sub
    const int row0 = blockIdx.x * 64;
    const int n0   = blockIdx.y * 64;

    const float* X;
    const float* W;
    __half* Y;
    if (row0 < BB * TE) {
        X = enc + (size_t)row0 * DM;  W = Wa;  Y = g_WencH + (size_t)row0 * DM;
    } else {
        const int r = row0 - BB * TE;
        X = dec + (size_t)r * DM;     W = Ua;  Y = g_UdecH + (size_t)r * DM;
    }

    float acc[4][4];
#pragma unroll
    for (int i = 0; i < 4; i++)
#pragma unroll
        for (int j = 0; j < 4; j++) acc[i][j] = 0.f;

    const int lm  = tid >> 2;         // 0..63
    const int lkq = tid & 3;          // 0..3
    const int lr  = tid >> 4;         // 0..15
    const int lc  = tid & 15;         // 0..15

    // prologue: tile 0
    float4 av = *(const float4*)(X + lm * DM + 4 * lkq);
    float4 bv = *(const float4*)(W + lr * DM + n0 + 4 * lc);
    sA[0][4 * lkq + 0][lm] = av.x;
    sA[0][4 * lkq + 1][lm] = av.y;
    sA[0][4 * lkq + 2][lm] = av.z;
    sA[0][4 * lkq + 3][lm] = av.w;
    *(float4*)(&sB[0][lr][4 * lc]) = bv;
    __syncthreads();

    int p = 0;
#pragma unroll 1
    for (int kt = 0; kt < 16; kt++) {
        float4 av2, bv2;
        if (kt < 15) {
            av2 = *(const float4*)(X + lm * DM + (kt + 1) * 16 + 4 * lkq);
            bv2 = *(const float4*)(W + ((kt + 1) * 16 + lr) * DM + n0 + 4 * lc);
        }
#pragma unroll
        for (int kk = 0; kk < 16; kk++) {
            float4 a = *(const float4*)(&sA[p][kk][ty * 4]);
            float4 b = *(const float4*)(&sB[p][kk][tx * 4]);
            acc[0][0] += a.x * b.x; acc[0][1] += a.x * b.y; acc[0][2] += a.x * b.z; acc[0][3] += a.x * b.w;
            acc[1][0] += a.y * b.x; acc[1][1] += a.y * b.y; acc[1][2] += a.y * b.z; acc[1][3] += a.y * b.w;
            acc[2][0] += a.z * b.x; acc[2][1] += a.z * b.y; acc[2][2] += a.z * b.z; acc[2][3] += a.z * b.w;
            acc[3][0] += a.w * b.x; acc[3][1] += a.w * b.y; acc[3][2] += a.w * b.z; acc[3][3] += a.w * b.w;
        }
        if (kt < 15) {
            sA[p ^ 1][4 * lkq + 0][lm] = av2.x;
            sA[p ^ 1][4 * lkq + 1][lm] = av2.y;
            sA[p ^ 1][4 * lkq + 2][lm] = av2.z;
            sA[p ^ 1][4 * lkq + 3][lm] = av2.w;
            *(float4*)(&sB[p ^ 1][lr][4 * lc]) = bv2;
        }
        __syncthreads();
        p ^= 1;
    }

#pragma unroll
    for (int i = 0; i < 4; i++) {
        __half2 p0 = __floats2half2_rn(acc[i][0], acc[i][1]);
        __half2 p1 = __floats2half2_rn(acc[i][2], acc[i][3]);
        uint2 o;
        o.x = *reinterpret_cast<unsigned*>(&p0);
        o.y = *reinterpret_cast<unsigned*>(&p1);
        *(uint2*)(Y + (ty * 4 + i) * DM + n0 + tx * 4) = o;
    }
}

// ---------------------------------------------------------------------------
// Main fused kernel: score (all-half2 inner loop) -> softmax -> context.
// Grid: B * (TD/TT) = 256 CTAs, 512 threads, 2 CTAs/SM.
// Phase B: warp w -> t = w&3, e-block (w>>2)*128. Per iter: 2 e-rows,
// 16 lanes each, lane owns 16 d's (8 half2). 4-stage shuffle -> 2 scores.
// ---------------------------------------------------------------------------
__global__ void __launch_bounds__(512, 2)
attn_main(const float* __restrict__ enc, const float* __restrict__ Va,
          float* __restrict__ out_ctx, float* __restrict__ out_attn) {
    __shared__ __align__(16) __half s_udec[TT * DM];   // 2 KB
    __shared__ float s_v[DM];                          // 1 KB
    __shared__ float s_score[TE][TT];                  // 8 KB, e-major
    __shared__ float s_red[TT * DM];                   // 4 KB (Phase D reduce)

    const int b    = blockIdx.x >> 6;
    const int t0   = (blockIdx.x & 63) * TT;
    const int tid  = threadIdx.x;
    const int warp = tid >> 5;
    const int lane = tid & 31;

    // ---- Phase A: stage Udec rows (half) + V (f32) into SMEM ----
    if (tid < 128)
        ((uint4*)s_udec)[tid] = ((const uint4*)(g_UdecH + (size_t)(b * TD + t0) * DM))[tid];
    else if (tid < 192)
        ((float4*)s_v)[tid - 128] = ((const float4*)Va)[tid - 128];
    __syncthreads();

    // ---- Phase B: scores, all-half2 inner loop ----
    {
        const int t   = warp & 3;
        const int eg  = warp >> 2;        // 0..3 (128 e's each)
        const int sub = lane & 15;        // d-chunk
        const int grp = lane >> 4;        // e parity within pair

        // u chunk: 16 halves from SMEM
        const __half2* up = (const __half2*)(s_udec + t * DM + sub * 16);
        __half2 u[8];
#pragma unroll
        for (int j = 0; j < 8; j++) u[j] = up[j];
        // v chunk: convert once
        const float* vp = s_v + sub * 16;
        __half2 v[8];
#pragma unroll
        for (int j = 0; j < 8; j++) v[j] = __floats2half2_rn(vp[2 * j], vp[2 * j + 1]);

        const uint4* wp = (const uint4*)(g_WencH + ((size_t)(b * TE) + eg * 128 + grp) * DM)
                          + sub * 2;
        uint4 wa = wp[0];
        uint4 wb = wp[1];
        int e = eg * 128 + grp;

#pragma unroll 1
        for (int i = 0; i < 64; i++) {
            const uint4 ca = wa, cb = wb;
            wp += 64;                     // advance 2 rows (512 halves)
            wa = wp[0];                   // padded overread on final iter
            wb = wp[1];

            const __half2* ha = (const __half2*)&ca;
            const __half2* hb = (const __half2*)&cb;
            __half2 acc0 = __hmul2(htanh2(__hadd2(ha[0], u[0])), v[0]);
            __half2 acc1 = __hmul2(htanh2(__hadd2(ha[1], u[1])), v[1]);
            acc0 = __hfma2(htanh2(__hadd2(ha[2], u[2])), v[2], acc0);
            acc1 = __hfma2(htanh2(__hadd2(ha[3], u[3])), v[3], acc1);
            acc0 = __hfma2(htanh2(__hadd2(hb[0], u[4])), v[4], acc0);
            acc1 = __hfma2(htanh2(__hadd2(hb[1], u[5])), v[5], acc1);
            acc0 = __hfma2(htanh2(__hadd2(hb[2], u[6])), v[6], acc0);
            acc1 = __hfma2(htanh2(__hadd2(hb[3], u[7])), v[7], acc1);

            float2 f0 = __half22float2(acc0);
            float2 f1 = __half22float2(acc1);
            float s = (f0.x + f0.y) + (f1.x + f1.y);
            s += __shfl_xor_sync(0xffffffffu, s, 8);
            s += __shfl_xor_sync(0xffffffffu, s, 4);
            s += __shfl_xor_sync(0xffffffffu, s, 2);
            s += __shfl_xor_sync(0xffffffffu, s, 1);
            if (sub == 0) s_score[e][t] = s;
            e += 2;
        }
    }
    __syncthreads();

    // ---- Phase C: softmax over e (warps 0..3, one t each) ----
    if (warp < TT) {
        const int t = warp;
        float vals[16];
        float mx = -1e30f;
#pragma unroll
        for (int k = 0; k < 16; k++) {
            vals[k] = s_score[lane + 32 * k][t];
            mx = fmaxf(mx, vals[k]);
        }
#pragma unroll
        for (int off = 16; off > 0; off >>= 1)
            mx = fmaxf(mx, __shfl_xor_sync(0xffffffffu, mx, off));
        float sum = 0.f;
#pragma unroll
        for (int k = 0; k < 16; k++) {
            vals[k] = exp2f((vals[k] - mx) * 1.4426950408889634f);
            sum += vals[k];
        }
#pragma unroll
        for (int off = 16; off > 0; off >>= 1)
            sum += __shfl_xor_sync(0xffffffffu, sum, off);
        const float inv = 1.0f / sum;
        float* arow = out_attn + ((size_t)(b * TD + t0 + t)) * TE;
#pragma unroll
        for (int k = 0; k < 16; k++) {
            const float w = vals[k] * inv;
            s_score[lane + 32 * k][t] = w;
            arow[lane + 32 * k] = w;
        }
    }
    __syncthreads();

    // ---- Phase D: context = attn @ enc (e-range split across thread halves) ----
    {
        const int d = tid & 255;
        const int h = tid >> 8;           // 0 or 1: e-half
        const float* encb = enc + (size_t)b * TE * DM + (size_t)h * 256 * DM;
        float a0 = 0.f, a1 = 0.f, a2 = 0.f, a3 = 0.f;
#pragma unroll 4
        for (int e = 0; e < 256; e++) {
            const float ev = __ldg(encb + (size_t)e * DM + d);
            float4 aw = *(const float4*)(&s_score[h * 256 + e][0]);
            a0 = fmaf(aw.x, ev, a0);
            a1 = fmaf(aw.y, ev, a1);
            a2 = fmaf(aw.z, ev, a2);
            a3 = fmaf(aw.w, ev, a3);
        }
        if (h == 1) {
            s_red[0 * 256 + d] = a0;
            s_red[1 * 256 + d] = a1;
            s_red[2 * 256 + d] = a2;
            s_red[3 * 256 + d] = a3;
        }
        __syncthreads();
        if (h == 0) {
            a0 += s_red[0 * 256 + d];
            a1 += s_red[1 * 256 + d];
            a2 += s_red[2 * 256 + d];
            a3 += s_red[3 * 256 + d];
            out_ctx[((size_t)(b * TD + t0 + 0)) * DM + d] = a0;
            out_ctx[((size_t)(b * TD + t0 + 1)) * DM + d] = a1;
            out_ctx[((size_t)(b * TD + t0 + 2)) * DM + d] = a2;
            out_ctx[((size_t)(b * TD + t0 + 3)) * DM + d] = a3;
        }
    }
}

extern "C" void kernel_launch(void* const* d_in, const int* in_sizes, int n_in,
                              void* d_out, int out_size) {
    const float* enc = (const float*)d_in[0];   // [4,512,256]
    const float* dec = (const float*)d_in[1];   // [4,256,256]
    const float* Wa  = (const float*)d_in[2];   // [256,256]
    const float* Ua  = (const float*)d_in[3];   // [256,256]
    const float* Va  = (const float*)d_in[4];   // [256,1]

    float* out      = (float*)d_out;
    float* out_ctx  = out;                          // [4,256,256]
    float* out_attn = out + (size_t)BB * TD * DM;   // [4,256,512]

    // Combined projections: 192 CTAs
    proj_gemm2<<<dim3((BB * TE + BB * TD) / 64, DM / 64), 256>>>(enc, dec, Wa, Ua);

    // Fused score/softmax/context: 256 CTAs
    attn_main<<<BB * (TD / TT), 512>>>(enc, Va, out_ctx, out_attn);
}

// round 4
// speedup vs baseline: 2.0760x; 1.0008x over previous
#include <cuda_runtime.h>
#include <cuda_bf16.h>
#include <cuda_fp16.h>

// Problem dims (fixed by reference setup_inputs)
#define BB 4
#define TE 512
#define TD 256
#define DM 256
#define TT 4   // t-rows per CTA in main kernel

// Scratch for projections in HALF (allocation-free: __device__ globals).
__device__ __align__(16) __half g_WencH[BB * TE * DM + 8 * DM];
__device__ __align__(16) __half g_UdecH[BB * TD * DM];

__device__ __forceinline__ __half2 htanh2(__half2 x) {
    unsigned xu = *reinterpret_cast<unsigned*>(&x);
    unsigned yu;
    asm("tanh.approx.f16x2 %0, %1;" : "=r"(yu) : "r"(xu));
    return *reinterpret_cast<__half2*>(&yu);
}

// ---------------------------------------------------------------------------
// Combined projection GEMM (enc@W_a and dec@U_a in one launch), HALF output.
// Rows 0..2047 -> g_WencH, rows 2048..3071 -> g_UdecH.
// BM=64, BN=64, BK=16, 256 threads, 4x4/thread, double-buffered SMEM.
// ---------------------------------------------------------------------------
__global__ void __launch_bounds__(256)
proj_gemm2(const float* __restrict__ enc, const float* __restrict__ dec,
           const float* __restrict__ Wa,  const float* __restrict__ Ua) {
    __shared__ float sA[2][16][64];   // sA[p][k][m]
    __shared__ float sB[2][16][64];   // sB[p][k][n]

    const int tid = threadIdx.x;
    const int tx = tid & 15;          // n-sub
    const int ty = tid >> 4;          // m-sub
    const int row0 = blockIdx.x * 64;
    const int n0   = blockIdx.y * 64;

    const float* X;
    const float* W;
    __half* Y;
    if (row0 < BB * TE) {
        X = enc + (size_t)row0 * DM;  W = Wa;  Y = g_WencH + (size_t)row0 * DM;
    } else {
        const int r = row0 - BB * TE;
        X = dec + (size_t)r * DM;     W = Ua;  Y = g_UdecH + (size_t)r * DM;
    }

    float acc[4][4];
#pragma unroll
    for (int i = 0; i < 4; i++)
#pragma unroll
        for (int j = 0; j < 4; j++) acc[i][j] = 0.f;

    const int lm  = tid >> 2;         // 0..63
    const int lkq = tid & 3;          // 0..3
    const int lr  = tid >> 4;         // 0..15
    const int lc  = tid & 15;         // 0..15

    // prologue: tile 0
    float4 av = *(const float4*)(X + lm * DM + 4 * lkq);
    float4 bv = *(const float4*)(W + lr * DM + n0 + 4 * lc);
    sA[0][4 * lkq + 0][lm] = av.x;
    sA[0][4 * lkq + 1][lm] = av.y;
    sA[0][4 * lkq + 2][lm] = av.z;
    sA[0][4 * lkq + 3][lm] = av.w;
    *(float4*)(&sB[0][lr][4 * lc]) = bv;
    __syncthreads();

    int p = 0;
#pragma unroll 1
    for (int kt = 0; kt < 16; kt++) {
        float4 av2, bv2;
        if (kt < 15) {
            av2 = *(const float4*)(X + lm * DM + (kt + 1) * 16 + 4 * lkq);
            bv2 = *(const float4*)(W + ((kt + 1) * 16 + lr) * DM + n0 + 4 * lc);
        }
#pragma unroll
        for (int kk = 0; kk < 16; kk++) {
            float4 a = *(const float4*)(&sA[p][kk][ty * 4]);
            float4 b = *(const float4*)(&sB[p][kk][tx * 4]);
            acc[0][0] += a.x * b.x; acc[0][1] += a.x * b.y; acc[0][2] += a.x * b.z; acc[0][3] += a.x * b.w;
            acc[1][0] += a.y * b.x; acc[1][1] += a.y * b.y; acc[1][2] += a.y * b.z; acc[1][3] += a.y * b.w;
            acc[2][0] += a.z * b.x; acc[2][1] += a.z * b.y; acc[2][2] += a.z * b.z; acc[2][3] += a.z * b.w;
            acc[3][0] += a.w * b.x; acc[3][1] += a.w * b.y; acc[3][2] += a.w * b.z; acc[3][3] += a.w * b.w;
        }
        if (kt < 15) {
            sA[p ^ 1][4 * lkq + 0][lm] = av2.x;
            sA[p ^ 1][4 * lkq + 1][lm] = av2.y;
            sA[p ^ 1][4 * lkq + 2][lm] = av2.z;
            sA[p ^ 1][4 * lkq + 3][lm] = av2.w;
            *(float4*)(&sB[p ^ 1][lr][4 * lc]) = bv2;
        }
        __syncthreads();
        p ^= 1;
    }

#pragma unroll
    for (int i = 0; i < 4; i++) {
        __half2 p0 = __floats2half2_rn(acc[i][0], acc[i][1]);
        __half2 p1 = __floats2half2_rn(acc[i][2], acc[i][3]);
        uint2 o;
        o.x = *reinterpret_cast<unsigned*>(&p0);
        o.y = *reinterpret_cast<unsigned*>(&p1);
        *(uint2*)(Y + (ty * 4 + i) * DM + n0 + tx * 4) = o;
    }
}

// ---------------------------------------------------------------------------
// Main fused kernel: score -> softmax -> context.
// Grid: B * (TD/TT) = 256 CTAs, 512 threads, 2 CTAs/SM.
// Phase B: warp w -> t = w&3, e-block (w>>2)*128; per iter 4 e-rows;
// lane: grp=lane>>3 (e in quad), sub=lane&7 (32-d chunk). 3-stage shuffle
// per 4 scores. MUFU-bound by design.
// ---------------------------------------------------------------------------
__global__ void __launch_bounds__(512, 2)
attn_main(const float* __restrict__ enc, const float* __restrict__ Va,
          float* __restrict__ out_ctx, float* __restrict__ out_attn) {
    __shared__ __align__(16) __half s_udec[TT * DM];   // 2 KB
    __shared__ __align__(16) __half s_vh[DM];          // 0.5 KB
    __shared__ float s_score[TE][TT];                  // 8 KB, e-major
    __shared__ float s_red[TT * DM];                   // 4 KB (Phase D reduce)

    const int b    = blockIdx.x >> 6;
    const int t0   = (blockIdx.x & 63) * TT;
    const int tid  = threadIdx.x;
    const int warp = tid >> 5;
    const int lane = tid & 31;

    // ---- Phase A: stage Udec rows (half) + V (converted to half) ----
    if (tid < 128) {
        ((uint4*)s_udec)[tid] = ((const uint4*)(g_UdecH + (size_t)(b * TD + t0) * DM))[tid];
    } else if (tid < 192) {
        const int i = tid - 128;      // 0..63
        float4 vf = ((const float4*)Va)[i];
        __half2 p0 = __floats2half2_rn(vf.x, vf.y);
        __half2 p1 = __floats2half2_rn(vf.z, vf.w);
        ((__half2*)s_vh)[2 * i]     = p0;
        ((__half2*)s_vh)[2 * i + 1] = p1;
    }
    __syncthreads();

    // ---- Phase B: scores ----
    {
        const int t   = warp & 3;
        const int eg  = warp >> 2;    // 0..3 (128 e's each)
        const int grp = lane >> 3;    // 0..3: e within quad
        const int sub = lane & 7;     // 0..7: 32-d chunk

        // hoist u chunk (16 half2) into regs
        __half2 u[16];
        {
            const uint4* up = (const uint4*)(s_udec + t * DM) + sub * 4;
            *(uint4*)(&u[0])  = up[0];
            *(uint4*)(&u[4])  = up[1];
            *(uint4*)(&u[8])  = up[2];
            *(uint4*)(&u[12]) = up[3];
        }
        const uint4* v4 = (const uint4*)s_vh + sub * 4;

        const uint4* wp = (const uint4*)g_WencH
                          + ((size_t)(b * TE) + eg * 128 + grp) * (DM / 8) + sub * 4;
        int e = eg * 128 + grp;

#pragma unroll 1
        for (int it = 0; it < 32; it++) {
            __half2 w[16];
            *(uint4*)(&w[0])  = wp[0];
            *(uint4*)(&w[4])  = wp[1];
            *(uint4*)(&w[8])  = wp[2];
            *(uint4*)(&w[12]) = wp[3];
            __half2 vv[16];
            *(uint4*)(&vv[0])  = v4[0];
            *(uint4*)(&vv[4])  = v4[1];
            *(uint4*)(&vv[8])  = v4[2];
            *(uint4*)(&vv[12]) = v4[3];

            __half2 acc0 = __hmul2(htanh2(__hadd2(w[0], u[0])), vv[0]);
            __half2 acc1 = __hmul2(htanh2(__hadd2(w[1], u[1])), vv[1]);
#pragma unroll
            for (int k = 2; k < 16; k += 2) {
                acc0 = __hfma2(htanh2(__hadd2(w[k],     u[k])),     vv[k],     acc0);
                acc1 = __hfma2(htanh2(__hadd2(w[k + 1], u[k + 1])), vv[k + 1], acc1);
            }
            __half2 accs = __hadd2(acc0, acc1);
            float2 f = __half22float2(accs);
            float s = f.x + f.y;
            s += __shfl_xor_sync(0xffffffffu, s, 4);
            s += __shfl_xor_sync(0xffffffffu, s, 2);
            s += __shfl_xor_sync(0xffffffffu, s, 1);
            if (sub == 0) s_score[e][t] = s;
            e  += 4;
            wp += 4 * (DM / 8);       // advance 4 rows
        }
    }
    __syncthreads();

    // ---- Phase C: softmax over e (warps 0..3, one t each) ----
    if (warp < TT) {
        const int t = warp;
        float vals[16];
        float mx = -1e30f;
#pragma unroll
        for (int k = 0; k < 16; k++) {
            vals[k] = s_score[lane + 32 * k][t];
            mx = fmaxf(mx, vals[k]);
        }
#pragma unroll
        for (int off = 16; off > 0; off >>= 1)
            mx = fmaxf(mx, __shfl_xor_sync(0xffffffffu, mx, off));
        float sum = 0.f;
#pragma unroll
        for (int k = 0; k < 16; k++) {
            vals[k] = exp2f((vals[k] - mx) * 1.4426950408889634f);
            sum += vals[k];
        }
#pragma unroll
        for (int off = 16; off > 0; off >>= 1)
            sum += __shfl_xor_sync(0xffffffffu, sum, off);
        const float inv = 1.0f / sum;
        float* arow = out_attn + ((size_t)(b * TD + t0 + t)) * TE;
#pragma unroll
        for (int k = 0; k < 16; k++) {
            const float w = vals[k] * inv;
            s_score[lane + 32 * k][t] = w;
            arow[lane + 32 * k] = w;
        }
    }
    __syncthreads();

    // ---- Phase D: context = attn @ enc (e-range split across thread halves) ----
    {
        const int d = tid & 255;
        const int h = tid >> 8;           // 0 or 1: e-half
        const float* encp = enc + (size_t)b * TE * DM + (size_t)h * 256 * DM + d;
        float a0 = 0.f, a1 = 0.f, a2 = 0.f, a3 = 0.f;
#pragma unroll 8
        for (int e = 0; e < 256; e++) {
            const float ev = __ldg(encp + (size_t)e * DM);
            float4 aw = *(const float4*)(&s_score[h * 256 + e][0]);
            a0 = fmaf(aw.x, ev, a0);
            a1 = fmaf(aw.y, ev, a1);
            a2 = fmaf(aw.z, ev, a2);
            a3 = fmaf(aw.w, ev, a3);
        }
        if (h == 1) {
            s_red[0 * 256 + d] = a0;
            s_red[1 * 256 + d] = a1;
            s_red[2 * 256 + d] = a2;
            s_red[3 * 256 + d] = a3;
        }
        __syncthreads();
        if (h == 0) {
            a0 += s_red[0 * 256 + d];
            a1 += s_red[1 * 256 + d];
            a2 += s_red[2 * 256 + d];
            a3 += s_red[3 * 256 + d];
            out_ctx[((size_t)(b * TD + t0 + 0)) * DM + d] = a0;
            out_ctx[((size_t)(b * TD + t0 + 1)) * DM + d] = a1;
            out_ctx[((size_t)(b * TD + t0 + 2)) * DM + d] = a2;
            out_ctx[((size_t)(b * TD + t0 + 3)) * DM + d] = a3;
        }
    }
}

extern "C" void kernel_launch(void* const* d_in, const int* in_sizes, int n_in,
                              void* d_out, int out_size) {
    const float* enc = (const float*)d_in[0];   // [4,512,256]
    const float* dec = (const float*)d_in[1];   // [4,256,256]
    const float* Wa  = (const float*)d_in[2];   // [256,256]
    const float* Ua  = (const float*)d_in[3];   // [256,256]
    const float* Va  = (const float*)d_in[4];   // [256,1]

    float* out      = (float*)d_out;
    float* out_ctx  = out;                          // [4,256,256]
    float* out_attn = out + (size_t)BB * TD * DM;   // [4,256,512]

    // Combined projections: 192 CTAs
    proj_gemm2<<<dim3((BB * TE + BB * TD) / 64, DM / 64), 256>>>(enc, dec, Wa, Ua);

    // Fused score/softmax/context: 256 CTAs
    attn_main<<<BB * (TD / TT), 512>>>(enc, Va, out_ctx, out_attn);
}

// round 5
// speedup vs baseline: 2.1435x; 1.0325x over previous
#include <cuda_runtime.h>
#include <cuda_bf16.h>
#include <cuda_fp16.h>

// Problem dims (fixed by reference setup_inputs)
#define BB 4
#define TE 512
#define TD 256
#define DM 256
#define TT 4   // t-rows per CTA in main kernel

// Scratch for projections in HALF (allocation-free: __device__ globals).
__device__ __align__(16) __half g_WencH[BB * TE * DM + 8 * DM];
__device__ __align__(16) __half g_UdecH[BB * TD * DM];

__device__ __forceinline__ __half2 htanh2(__half2 x) {
    unsigned xu = *reinterpret_cast<unsigned*>(&x);
    unsigned yu;
    asm("tanh.approx.f16x2 %0, %1;" : "=r"(yu) : "r"(xu));
    return *reinterpret_cast<__half2*>(&yu);
}

// ---------------------------------------------------------------------------
// Combined projection GEMM (enc@W_a and dec@U_a in one launch), HALF output.
// Rows 0..2047 -> g_WencH, rows 2048..3071 -> g_UdecH.
// BM=64, BN=64, BK=16, 256 threads, 4x4/thread, double-buffered SMEM.
// ---------------------------------------------------------------------------
__global__ void __launch_bounds__(256)
proj_gemm2(const float* __restrict__ enc, const float* __restrict__ dec,
           const float* __restrict__ Wa,  const float* __restrict__ Ua) {
    __shared__ float sA[2][16][64];   // sA[p][k][m]
    __shared__ float sB[2][16][64];   // sB[p][k][n]

    const int tid = threadIdx.x;
    const int tx = tid & 15;          // n-sub
    const int ty = tid >> 4;          // m-sub
    const int row0 = blockIdx.x * 64;
    const int n0   = blockIdx.y * 64;

    const float* X;
    const float* W;
    __half* Y;
    if (row0 < BB * TE) {
        X = enc + (size_t)row0 * DM;  W = Wa;  Y = g_WencH + (size_t)row0 * DM;
    } else {
        const int r = row0 - BB * TE;
        X = dec + (size_t)r * DM;     W = Ua;  Y = g_UdecH + (size_t)r * DM;
    }

    float acc[4][4];
#pragma unroll
    for (int i = 0; i < 4; i++)
#pragma unroll
        for (int j = 0; j < 4; j++) acc[i][j] = 0.f;

    const int lm  = tid >> 2;         // 0..63
    const int lkq = tid & 3;          // 0..3
    const int lr  = tid >> 4;         // 0..15
    const int lc  = tid & 15;         // 0..15

    // prologue: tile 0
    float4 av = *(const float4*)(X + lm * DM + 4 * lkq);
    float4 bv = *(const float4*)(W + lr * DM + n0 + 4 * lc);
    sA[0][4 * lkq + 0][lm] = av.x;
    sA[0][4 * lkq + 1][lm] = av.y;
    sA[0][4 * lkq + 2][lm] = av.z;
    sA[0][4 * lkq + 3][lm] = av.w;
    *(float4*)(&sB[0][lr][4 * lc]) = bv;
    __syncthreads();

    int p = 0;
#pragma unroll 1
    for (int kt = 0; kt < 16; kt++) {
        float4 av2, bv2;
        if (kt < 15) {
            av2 = *(const float4*)(X + lm * DM + (kt + 1) * 16 + 4 * lkq);
            bv2 = *(const float4*)(W + ((kt + 1) * 16 + lr) * DM + n0 + 4 * lc);
        }
#pragma unroll
        for (int kk = 0; kk < 16; kk++) {
            float4 a = *(const float4*)(&sA[p][kk][ty * 4]);
            float4 b = *(const float4*)(&sB[p][kk][tx * 4]);
            acc[0][0] += a.x * b.x; acc[0][1] += a.x * b.y; acc[0][2] += a.x * b.z; acc[0][3] += a.x * b.w;
            acc[1][0] += a.y * b.x; acc[1][1] += a.y * b.y; acc[1][2] += a.y * b.z; acc[1][3] += a.y * b.w;
            acc[2][0] += a.z * b.x; acc[2][1] += a.z * b.y; acc[2][2] += a.z * b.z; acc[2][3] += a.z * b.w;
            acc[3][0] += a.w * b.x; acc[3][1] += a.w * b.y; acc[3][2] += a.w * b.z; acc[3][3] += a.w * b.w;
        }
        if (kt < 15) {
            sA[p ^ 1][4 * lkq + 0][lm] = av2.x;
            sA[p ^ 1][4 * lkq + 1][lm] = av2.y;
            sA[p ^ 1][4 * lkq + 2][lm] = av2.z;
            sA[p ^ 1][4 * lkq + 3][lm] = av2.w;
            *(float4*)(&sB[p ^ 1][lr][4 * lc]) = bv2;
        }
        __syncthreads();
        p ^= 1;
    }

#pragma unroll
    for (int i = 0; i < 4; i++) {
        __half2 p0 = __floats2half2_rn(acc[i][0], acc[i][1]);
        __half2 p1 = __floats2half2_rn(acc[i][2], acc[i][3]);
        uint2 o;
        o.x = *reinterpret_cast<unsigned*>(&p0);
        o.y = *reinterpret_cast<unsigned*>(&p1);
        *(uint2*)(Y + (ty * 4 + i) * DM + n0 + tx * 4) = o;
    }
}

// ---------------------------------------------------------------------------
// Main fused kernel: score -> softmax -> context.
// Grid: B * (TD/TT) = 256 CTAs, 512 threads, 2 CTAs/SM.
// Phase B: warp w -> e-block [w*32, w*32+32), ALL 4 t's (w reused 4x in regs).
// Lane: e_idx = lane>>4 (2 e-rows/iter), d_sub = lane&15 (16 d's each).
// ---------------------------------------------------------------------------
__global__ void __launch_bounds__(512, 2)
attn_main(const float* __restrict__ enc, const float* __restrict__ Va,
          float* __restrict__ out_ctx, float* __restrict__ out_attn) {
    __shared__ __align__(16) __half s_udec[TT * DM];       // 2 KB
    __shared__ __align__(16) __half s_vh[DM];              // 0.5 KB
    __shared__ __align__(16) float s_score[TE][TT];        // 8 KB, e-major
    __shared__ float s_red[TT * DM];                       // 4 KB (Phase D)

    const int b    = blockIdx.x >> 6;
    const int t0   = (blockIdx.x & 63) * TT;
    const int tid  = threadIdx.x;
    const int warp = tid >> 5;
    const int lane = tid & 31;

    // ---- Phase A: stage Udec rows (half) + V (converted to half) ----
    if (tid < 128) {
        ((uint4*)s_udec)[tid] = ((const uint4*)(g_UdecH + (size_t)(b * TD + t0) * DM))[tid];
    } else if (tid < 192) {
        const int i = tid - 128;      // 0..63
        float4 vf = ((const float4*)Va)[i];
        ((__half2*)s_vh)[2 * i]     = __floats2half2_rn(vf.x, vf.y);
        ((__half2*)s_vh)[2 * i + 1] = __floats2half2_rn(vf.z, vf.w);
    }
    __syncthreads();

    // ---- Phase B: scores (each w-load reused for all 4 t's) ----
    {
        const int e_idx = lane >> 4;      // 0..1
        const int d_sub = lane & 15;      // 0..15, owns 16 d's
        const int eb    = warp * 32;      // e-block

        // hoist u for all 4 t's: 4 x 8 half2 = 32 regs
        __half2 u[4][8];
#pragma unroll
        for (int t = 0; t < 4; t++) {
            const uint4* up = (const uint4*)(s_udec + t * DM + d_sub * 16);
            *(uint4*)(&u[t][0]) = up[0];
            *(uint4*)(&u[t][4]) = up[1];
        }
        // hoist v: 8 half2
        __half2 v[8];
        {
            const uint4* vp = (const uint4*)(s_vh + d_sub * 16);
            *(uint4*)(&v[0]) = vp[0];
            *(uint4*)(&v[4]) = vp[1];
        }

        const uint4* wp = (const uint4*)g_WencH
                          + ((size_t)(b * TE) + eb + e_idx) * (DM / 8) + d_sub * 2;

#pragma unroll 1
        for (int it = 0; it < 16; it++) {
            const int e = eb + 2 * it + e_idx;
            __half2 w[8];
            *(uint4*)(&w[0]) = wp[0];
            *(uint4*)(&w[4]) = wp[1];
            wp += 2 * (DM / 8);           // advance 2 e-rows

            float s[4];
#pragma unroll
            for (int t = 0; t < 4; t++) {
                __half2 a0 = __hmul2(htanh2(__hadd2(w[0], u[t][0])), v[0]);
                __half2 a1 = __hmul2(htanh2(__hadd2(w[1], u[t][1])), v[1]);
                a0 = __hfma2(htanh2(__hadd2(w[2], u[t][2])), v[2], a0);
                a1 = __hfma2(htanh2(__hadd2(w[3], u[t][3])), v[3], a1);
                a0 = __hfma2(htanh2(__hadd2(w[4], u[t][4])), v[4], a0);
                a1 = __hfma2(htanh2(__hadd2(w[5], u[t][5])), v[5], a1);
                a0 = __hfma2(htanh2(__hadd2(w[6], u[t][6])), v[6], a0);
                a1 = __hfma2(htanh2(__hadd2(w[7], u[t][7])), v[7], a1);
                float2 f = __half22float2(__hadd2(a0, a1));
                s[t] = f.x + f.y;
            }
            // butterfly over the 16 d_sub lanes (stays within e_idx half)
#pragma unroll
            for (int off = 8; off > 0; off >>= 1) {
                s[0] += __shfl_xor_sync(0xffffffffu, s[0], off);
                s[1] += __shfl_xor_sync(0xffffffffu, s[1], off);
                s[2] += __shfl_xor_sync(0xffffffffu, s[2], off);
                s[3] += __shfl_xor_sync(0xffffffffu, s[3], off);
            }
            if (d_sub == 0)
                *(float4*)(&s_score[e][0]) = make_float4(s[0], s[1], s[2], s[3]);
        }
    }
    __syncthreads();

    // ---- Phase C: softmax over e (warps 0..3, one t each) ----
    if (warp < TT) {
        const int t = warp;
        float vals[16];
        float mx = -1e30f;
#pragma unroll
        for (int k = 0; k < 16; k++) {
            vals[k] = s_score[lane + 32 * k][t];
            mx = fmaxf(mx, vals[k]);
        }
#pragma unroll
        for (int off = 16; off > 0; off >>= 1)
            mx = fmaxf(mx, __shfl_xor_sync(0xffffffffu, mx, off));
        float sum = 0.f;
#pragma unroll
        for (int k = 0; k < 16; k++) {
            vals[k] = exp2f((vals[k] - mx) * 1.4426950408889634f);
            sum += vals[k];
        }
#pragma unroll
        for (int off = 16; off > 0; off >>= 1)
            sum += __shfl_xor_sync(0xffffffffu, sum, off);
        const float inv = 1.0f / sum;
        float* arow = out_attn + ((size_t)(b * TD + t0 + t)) * TE;
#pragma unroll
        for (int k = 0; k < 16; k++) {
            const float w = vals[k] * inv;
            s_score[lane + 32 * k][t] = w;
            arow[lane + 32 * k] = w;
        }
    }
    __syncthreads();

    // ---- Phase D: context = attn @ enc (e-range split across thread halves) ----
    {
        const int d = tid & 255;
        const int h = tid >> 8;           // 0 or 1: e-half
        const float* encp = enc + (size_t)b * TE * DM + (size_t)h * 256 * DM + d;
        float a0 = 0.f, a1 = 0.f, a2 = 0.f, a3 = 0.f;
#pragma unroll 8
        for (int e = 0; e < 256; e++) {
            const float ev = __ldg(encp + (size_t)e * DM);
            float4 aw = *(const float4*)(&s_score[h * 256 + e][0]);
            a0 = fmaf(aw.x, ev, a0);
            a1 = fmaf(aw.y, ev, a1);
            a2 = fmaf(aw.z, ev, a2);
            a3 = fmaf(aw.w, ev, a3);
        }
        if (h == 1) {
            s_red[0 * 256 + d] = a0;
            s_red[1 * 256 + d] = a1;
            s_red[2 * 256 + d] = a2;
            s_red[3 * 256 + d] = a3;
        }
        __syncthreads();
        if (h == 0) {
            a0 += s_red[0 * 256 + d];
            a1 += s_red[1 * 256 + d];
            a2 += s_red[2 * 256 + d];
            a3 += s_red[3 * 256 + d];
            out_ctx[((size_t)(b * TD + t0 + 0)) * DM + d] = a0;
            out_ctx[((size_t)(b * TD + t0 + 1)) * DM + d] = a1;
            out_ctx[((size_t)(b * TD + t0 + 2)) * DM + d] = a2;
            out_ctx[((size_t)(b * TD + t0 + 3)) * DM + d] = a3;
        }
    }
}

extern "C" void kernel_launch(void* const* d_in, const int* in_sizes, int n_in,
                              void* d_out, int out_size) {
    const float* enc = (const float*)d_in[0];   // [4,512,256]
    const float* dec = (const float*)d_in[1];   // [4,256,256]
    const float* Wa  = (const float*)d_in[2];   // [256,256]
    const float* Ua  = (const float*)d_in[3];   // [256,256]
    const float* Va  = (const float*)d_in[4];   // [256,1]

    float* out      = (float*)d_out;
    float* out_ctx  = out;                          // [4,256,256]
    float* out_attn = out + (size_t)BB * TD * DM;   // [4,256,512]

    // Combined projections: 192 CTAs
    proj_gemm2<<<dim3((BB * TE + BB * TD) / 64, DM / 64), 256>>>(enc, dec, Wa, Ua);

    // Fused score/softmax/context: 256 CTAs
    attn_main<<<BB * (TD / TT), 512>>>(enc, Va, out_ctx, out_attn);
}

// round 6
// speedup vs baseline: 2.1756x; 1.0150x over previous
#include <cuda_runtime.h>
#include <cuda_bf16.h>
#include <cuda_fp16.h>

// Problem dims (fixed by reference setup_inputs)
#define BB 4
#define TE 512
#define TD 256
#define DM 256
#define TT 4   // t-rows per CTA in main kernel

// Scratch for projections in HALF (allocation-free: __device__ globals).
// +8*DM pad: attn_main prefetch overreads past the end (values unused).
__device__ __align__(16) __half g_WencH[BB * TE * DM + 8 * DM];
__device__ __align__(16) __half g_UdecH[BB * TD * DM];

__device__ __forceinline__ __half2 htanh2(__half2 x) {
    unsigned xu = *reinterpret_cast<unsigned*>(&x);
    unsigned yu;
    asm("tanh.approx.f16x2 %0, %1;" : "=r"(yu) : "r"(xu));
    return *reinterpret_cast<__half2*>(&yu);
}

// ---------------------------------------------------------------------------
// Combined projection GEMM (enc@W_a and dec@U_a in one launch), HALF output.
// Rows 0..2047 -> g_WencH, rows 2048..3071 -> g_UdecH.
// BM=64, BN=64, BK=16, 256 threads, 4x4/thread, double-buffered SMEM.
// ---------------------------------------------------------------------------
__global__ void __launch_bounds__(256)
proj_gemm2(const float* __restrict__ enc, const float* __restrict__ dec,
           const float* __restrict__ Wa,  const float* __restrict__ Ua) {
    __shared__ float sA[2][16][64];   // sA[p][k][m]
    __shared__ float sB[2][16][64];   // sB[p][k][n]

    const int tid = threadIdx.x;
    const int tx = tid & 15;          // n-sub
    const int ty = tid >> 4;          // m-sub
    const int row0 = blockIdx.x * 64;
    const int n0   = blockIdx.y * 64;

    const float* X;
    const float* W;
    __half* Y;
    if (row0 < BB * TE) {
        X = enc + (size_t)row0 * DM;  W = Wa;  Y = g_WencH + (size_t)row0 * DM;
    } else {
        const int r = row0 - BB * TE;
        X = dec + (size_t)r * DM;     W = Ua;  Y = g_UdecH + (size_t)r * DM;
    }

    float acc[4][4];
#pragma unroll
    for (int i = 0; i < 4; i++)
#pragma unroll
        for (int j = 0; j < 4; j++) acc[i][j] = 0.f;

    const int lm  = tid >> 2;         // 0..63
    const int lkq = tid & 3;          // 0..3
    const int lr  = tid >> 4;         // 0..15
    const int lc  = tid & 15;         // 0..15

    // prologue: tile 0
    float4 av = *(const float4*)(X + lm * DM + 4 * lkq);
    float4 bv = *(const float4*)(W + lr * DM + n0 + 4 * lc);
    sA[0][4 * lkq + 0][lm] = av.x;
    sA[0][4 * lkq + 1][lm] = av.y;
    sA[0][4 * lkq + 2][lm] = av.z;
    sA[0][4 * lkq + 3][lm] = av.w;
    *(float4*)(&sB[0][lr][4 * lc]) = bv;
    __syncthreads();

    int p = 0;
#pragma unroll 1
    for (int kt = 0; kt < 16; kt++) {
        float4 av2, bv2;
        if (kt < 15) {
            av2 = *(const float4*)(X + lm * DM + (kt + 1) * 16 + 4 * lkq);
            bv2 = *(const float4*)(W + ((kt + 1) * 16 + lr) * DM + n0 + 4 * lc);
        }
#pragma unroll
        for (int kk = 0; kk < 16; kk++) {
            float4 a = *(const float4*)(&sA[p][kk][ty * 4]);
            float4 b = *(const float4*)(&sB[p][kk][tx * 4]);
            acc[0][0] += a.x * b.x; acc[0][1] += a.x * b.y; acc[0][2] += a.x * b.z; acc[0][3] += a.x * b.w;
            acc[1][0] += a.y * b.x; acc[1][1] += a.y * b.y; acc[1][2] += a.y * b.z; acc[1][3] += a.y * b.w;
            acc[2][0] += a.z * b.x; acc[2][1] += a.z * b.y; acc[2][2] += a.z * b.z; acc[2][3] += a.z * b.w;
            acc[3][0] += a.w * b.x; acc[3][1] += a.w * b.y; acc[3][2] += a.w * b.z; acc[3][3] += a.w * b.w;
        }
        if (kt < 15) {
            sA[p ^ 1][4 * lkq + 0][lm] = av2.x;
            sA[p ^ 1][4 * lkq + 1][lm] = av2.y;
            sA[p ^ 1][4 * lkq + 2][lm] = av2.z;
            sA[p ^ 1][4 * lkq + 3][lm] = av2.w;
            *(float4*)(&sB[p ^ 1][lr][4 * lc]) = bv2;
        }
        __syncthreads();
        p ^= 1;
    }

#pragma unroll
    for (int i = 0; i < 4; i++) {
        __half2 p0 = __floats2half2_rn(acc[i][0], acc[i][1]);
        __half2 p1 = __floats2half2_rn(acc[i][2], acc[i][3]);
        uint2 o;
        o.x = *reinterpret_cast<unsigned*>(&p0);
        o.y = *reinterpret_cast<unsigned*>(&p1);
        *(uint2*)(Y + (ty * 4 + i) * DM + n0 + tx * 4) = o;
    }
}

// ---------------------------------------------------------------------------
// Main fused kernel: score -> softmax -> context.
// Grid: B * (TD/TT) = 256 CTAs, 512 threads, 2 CTAs/SM.
// Phase B: warp w -> e-block [w*32, w*32+32), ALL 4 t's per w-load.
// Lane: e_idx = lane>>4 (2 e-rows/iter), d_sub = lane&15 (16 d's each).
// u read from SMEM per t (frees regs); next-iter w prefetched into regs.
// ---------------------------------------------------------------------------
__global__ void __launch_bounds__(512, 2)
attn_main(const float* __restrict__ enc, const float* __restrict__ Va,
          float* __restrict__ out_ctx, float* __restrict__ out_attn) {
    __shared__ __align__(16) __half s_udec[TT * DM];       // 2 KB
    __shared__ __align__(16) __half s_vh[DM];              // 0.5 KB
    __shared__ __align__(16) float s_score[TE][TT];        // 8 KB, e-major
    __shared__ float s_red[TT * DM];                       // 4 KB (Phase D)

    const int b    = blockIdx.x >> 6;
    const int t0   = (blockIdx.x & 63) * TT;
    const int tid  = threadIdx.x;
    const int warp = tid >> 5;
    const int lane = tid & 31;

    // ---- Phase A: stage Udec rows (half) + V (converted to half) ----
    if (tid < 128) {
        ((uint4*)s_udec)[tid] = ((const uint4*)(g_UdecH + (size_t)(b * TD + t0) * DM))[tid];
    } else if (tid < 192) {
        const int i = tid - 128;      // 0..63
        float4 vf = ((const float4*)Va)[i];
        ((__half2*)s_vh)[2 * i]     = __floats2half2_rn(vf.x, vf.y);
        ((__half2*)s_vh)[2 * i + 1] = __floats2half2_rn(vf.z, vf.w);
    }
    __syncthreads();

    // ---- Phase B: scores (w reused for all 4 t's; w prefetched) ----
    {
        const int e_idx = lane >> 4;      // 0..1
        const int d_sub = lane & 15;      // 0..15, owns 16 d's
        const int eb    = warp * 32;      // e-block

        // hoist v: 8 half2 (16 regs as 4x uint4 halves)
        __half2 v[8];
        {
            const uint4* vp = (const uint4*)(s_vh + d_sub * 16);
            *(uint4*)(&v[0]) = vp[0];
            *(uint4*)(&v[4]) = vp[1];
        }
        // SMEM pointers for u per t
        const uint4* up0 = (const uint4*)(s_udec + 0 * DM + d_sub * 16);
        const uint4* up1 = (const uint4*)(s_udec + 1 * DM + d_sub * 16);
        const uint4* up2 = (const uint4*)(s_udec + 2 * DM + d_sub * 16);
        const uint4* up3 = (const uint4*)(s_udec + 3 * DM + d_sub * 16);

        const uint4* wp = (const uint4*)g_WencH
                          + ((size_t)(b * TE) + eb + e_idx) * (DM / 8) + d_sub * 2;

        // prefetch iter 0
        uint4 pa = wp[0];
        uint4 pb = wp[1];

#pragma unroll 1
        for (int it = 0; it < 16; it++) {
            const int e = eb + 2 * it + e_idx;
            const uint4 ca = pa, cb = pb;
            wp += 2 * (DM / 8);           // advance 2 e-rows
            pa = wp[0];                   // padded overread on final iter
            pb = wp[1];

            __half2 w[8];
            *(uint4*)(&w[0]) = ca;
            *(uint4*)(&w[4]) = cb;

            float s[4];
#pragma unroll
            for (int t = 0; t < 4; t++) {
                const uint4* up = (t == 0) ? up0 : (t == 1) ? up1 : (t == 2) ? up2 : up3;
                __half2 u[8];
                *(uint4*)(&u[0]) = up[0];
                *(uint4*)(&u[4]) = up[1];

                __half2 a0 = __hmul2(htanh2(__hadd2(w[0], u[0])), v[0]);
                __half2 a1 = __hmul2(htanh2(__hadd2(w[1], u[1])), v[1]);
                a0 = __hfma2(htanh2(__hadd2(w[2], u[2])), v[2], a0);
                a1 = __hfma2(htanh2(__hadd2(w[3], u[3])), v[3], a1);
                a0 = __hfma2(htanh2(__hadd2(w[4], u[4])), v[4], a0);
                a1 = __hfma2(htanh2(__hadd2(w[5], u[5])), v[5], a1);
                a0 = __hfma2(htanh2(__hadd2(w[6], u[6])), v[6], a0);
                a1 = __hfma2(htanh2(__hadd2(w[7], u[7])), v[7], a1);
                float2 f = __half22float2(__hadd2(a0, a1));
                s[t] = f.x + f.y;
            }
            // butterfly over the 16 d_sub lanes (stays within e_idx half)
#pragma unroll
            for (int off = 8; off > 0; off >>= 1) {
                s[0] += __shfl_xor_sync(0xffffffffu, s[0], off);
                s[1] += __shfl_xor_sync(0xffffffffu, s[1], off);
                s[2] += __shfl_xor_sync(0xffffffffu, s[2], off);
                s[3] += __shfl_xor_sync(0xffffffffu, s[3], off);
            }
            if (d_sub == 0)
                *(float4*)(&s_score[e][0]) = make_float4(s[0], s[1], s[2], s[3]);
        }
    }
    __syncthreads();

    // ---- Phase C: softmax over e (warps 0..3, one t each) ----
    if (warp < TT) {
        const int t = warp;
        float vals[16];
        float mx = -1e30f;
#pragma unroll
        for (int k = 0; k < 16; k++) {
            vals[k] = s_score[lane + 32 * k][t];
            mx = fmaxf(mx, vals[k]);
        }
#pragma unroll
        for (int off = 16; off > 0; off >>= 1)
            mx = fmaxf(mx, __shfl_xor_sync(0xffffffffu, mx, off));
        float sum = 0.f;
#pragma unroll
        for (int k = 0; k < 16; k++) {
            vals[k] = exp2f((vals[k] - mx) * 1.4426950408889634f);
            sum += vals[k];
        }
#pragma unroll
        for (int off = 16; off > 0; off >>= 1)
            sum += __shfl_xor_sync(0xffffffffu, sum, off);
        const float inv = 1.0f / sum;
        float* arow = out_attn + ((size_t)(b * TD + t0 + t)) * TE;
#pragma unroll
        for (int k = 0; k < 16; k++) {
            const float w = vals[k] * inv;
            s_score[lane + 32 * k][t] = w;
            arow[lane + 32 * k] = w;
        }
    }
    __syncthreads();

    // ---- Phase D: context = attn @ enc (e-range split across thread halves) ----
    {
        const int d = tid & 255;
        const int h = tid >> 8;           // 0 or 1: e-half
        const float* encp = enc + (size_t)b * TE * DM + (size_t)h * 256 * DM + d;
        float a0 = 0.f, a1 = 0.f, a2 = 0.f, a3 = 0.f;
#pragma unroll 8
        for (int e = 0; e < 256; e++) {
            const float ev = __ldg(encp + (size_t)e * DM);
            float4 aw = *(const float4*)(&s_score[h * 256 + e][0]);
            a0 = fmaf(aw.x, ev, a0);
            a1 = fmaf(aw.y, ev, a1);
            a2 = fmaf(aw.z, ev, a2);
            a3 = fmaf(aw.w, ev, a3);
        }
        if (h == 1) {
            s_red[0 * 256 + d] = a0;
            s_red[1 * 256 + d] = a1;
            s_red[2 * 256 + d] = a2;
            s_red[3 * 256 + d] = a3;
        }
        __syncthreads();
        if (h == 0) {
            a0 += s_red[0 * 256 + d];
            a1 += s_red[1 * 256 + d];
            a2 += s_red[2 * 256 + d];
            a3 += s_red[3 * 256 + d];
            out_ctx[((size_t)(b * TD + t0 + 0)) * DM + d] = a0;
            out_ctx[((size_t)(b * TD + t0 + 1)) * DM + d] = a1;
            out_ctx[((size_t)(b * TD + t0 + 2)) * DM + d] = a2;
            out_ctx[((size_t)(b * TD + t0 + 3)) * DM + d] = a3;
        }
    }
}

extern "C" void kernel_launch(void* const* d_in, const int* in_sizes, int n_in,
                              void* d_out, int out_size) {
    const float* enc = (const float*)d_in[0];   // [4,512,256]
    const float* dec = (const float*)d_in[1];   // [4,256,256]
    const float* Wa  = (const float*)d_in[2];   // [256,256]
    const float* Ua  = (const float*)d_in[3];   // [256,256]
    const float* Va  = (const float*)d_in[4];   // [256,1]

    float* out      = (float*)d_out;
    float* out_ctx  = out;                          // [4,256,256]
    float* out_attn = out + (size_t)BB * TD * DM;   // [4,256,512]

    // Combined projections: 192 CTAs
    proj_gemm2<<<dim3((BB * TE + BB * TD) / 64, DM / 64), 256>>>(enc, dec, Wa, Ua);

    // Fused score/softmax/context: 256 CTAs
    attn_main<<<BB * (TD / TT), 512>>>(enc, Va, out_ctx, out_attn);
}